// round 9
// baseline (speedup 1.0000x reference)
#include <cuda_runtime.h>

#define NN   100000
#define EMAX 1600000
#define INC  128
#define HID  64
#define OUTC 32
#define SCB  256                      // scan block size (elements == threads)

// Scratch (device globals — no allocation allowed in kernel_launch)
__device__ float g_dinv[NN];
__device__ int   g_cnt[NN];
__device__ int   g_off[NN + 1];
__device__ int   g_rank[EMAX];        // in-bucket rank of each edge
__device__ int   g_part[(NN + SCB - 1) / SCB + 1];
__device__ int2  g_edge2[EMAX];       // CSR-permuted {src, norm-bits} per edge
__device__ float g_h1[NN * HID];      // x @ W1
__device__ float g_o1[NN * HID];      // aggregated layer-1 output (pre-relu)
__device__ float g_h2[NN * OUTC];     // relu(o1) @ W2

// ---------------------------------------------------------------------------
// degree count + in-bucket rank (int atomics, int4-vectorized index loads)
// ---------------------------------------------------------------------------
__global__ void k_cnt_edge(const int* __restrict__ dst, int* __restrict__ cnt,
                           int* __restrict__ rank, int E) {
    int i = blockIdx.x * blockDim.x + threadIdx.x;
    if (i * 4 >= E) return;
    if (i * 4 + 3 < E) {
        int4 d4 = *(const int4*)&dst[i * 4];
        int4 r4;
        r4.x = atomicAdd(&cnt[d4.x], 1);
        r4.y = atomicAdd(&cnt[d4.y], 1);
        r4.z = atomicAdd(&cnt[d4.z], 1);
        r4.w = atomicAdd(&cnt[d4.w], 1);
        *(int4*)&rank[i * 4] = r4;
    } else {
        for (int e = i * 4; e < E; e++) rank[e] = atomicAdd(&cnt[dst[e]], 1);
    }
}

// ---------------------------------------------------------------------------
// Phase 1: per-block partial sums of cnt (coalesced, full chip)
// ---------------------------------------------------------------------------
__global__ __launch_bounds__(SCB) void k_part(const int* __restrict__ cnt,
                                              int* __restrict__ part, int n) {
    __shared__ int wsum[SCB / 32];
    const int i = blockIdx.x * SCB + threadIdx.x;
    const int lane = threadIdx.x & 31, wid = threadIdx.x >> 5;
    int v = (i < n) ? cnt[i] : 0;
#pragma unroll
    for (int ofs = 16; ofs > 0; ofs >>= 1)
        v += __shfl_down_sync(0xffffffffu, v, ofs);
    if (lane == 0) wsum[wid] = v;
    __syncthreads();
    if (wid == 0) {
        int w = (lane < SCB / 32) ? wsum[lane] : 0;
#pragma unroll
        for (int ofs = 16; ofs > 0; ofs >>= 1)
            w += __shfl_down_sync(0xffffffffu, w, ofs);
        if (lane == 0) part[blockIdx.x] = w;
    }
}

// ---------------------------------------------------------------------------
// Phase 2: single-block exclusive scan over block partials (~391 values),
// warp-shuffle scan (512 threads, 16 warps, 2 syncs).
// ---------------------------------------------------------------------------
__global__ __launch_bounds__(512) void k_scan_part(int* __restrict__ part,
                                                   int* __restrict__ off,
                                                   int nb, int n) {
    __shared__ int wtot[16];
    const int t = threadIdx.x;
    const int lane = t & 31, wid = t >> 5;
    int c = (t < nb) ? part[t] : 0;

    int v = c;
#pragma unroll
    for (int ofs = 1; ofs < 32; ofs <<= 1) {
        int u = __shfl_up_sync(0xffffffffu, v, ofs);
        if (lane >= ofs) v += u;
    }
    if (lane == 31) wtot[wid] = v;
    __syncthreads();
    if (wid == 0) {
        int w = (lane < 16) ? wtot[lane] : 0;
#pragma unroll
        for (int ofs = 1; ofs < 16; ofs <<= 1) {
            int u = __shfl_up_sync(0xffffffffu, w, ofs);
            if (lane >= ofs) w += u;
        }
        if (lane < 16) wtot[lane] = w;
    }
    __syncthreads();

    int incl = v + (wid > 0 ? wtot[wid - 1] : 0);
    if (t < nb) part[t] = incl - c;          // exclusive block offset
    if (t == 511) off[n] = wtot[15];         // total = E
}

// ---------------------------------------------------------------------------
// Phase 3: block-local exclusive scan + apply block offset; write off/dinv.
// ---------------------------------------------------------------------------
__global__ __launch_bounds__(SCB) void k_apply(const int* __restrict__ cnt,
                                               const int* __restrict__ part,
                                               int* __restrict__ off,
                                               float* __restrict__ dinv, int n) {
    __shared__ int wtot[SCB / 32];
    const int i = blockIdx.x * SCB + threadIdx.x;
    const int lane = threadIdx.x & 31, wid = threadIdx.x >> 5;
    int c = (i < n) ? cnt[i] : 0;

    int v = c;
#pragma unroll
    for (int ofs = 1; ofs < 32; ofs <<= 1) {
        int u = __shfl_up_sync(0xffffffffu, v, ofs);
        if (lane >= ofs) v += u;
    }
    if (lane == 31) wtot[wid] = v;
    __syncthreads();
    if (wid == 0) {
        int w = (lane < SCB / 32) ? wtot[lane] : 0;
#pragma unroll
        for (int ofs = 1; ofs < SCB / 32; ofs <<= 1) {
            int u = __shfl_up_sync(0xffffffffu, w, ofs);
            if (lane >= ofs) w += u;
        }
        if (lane < SCB / 32) wtot[lane] = w;
    }
    __syncthreads();

    int excl = v - c + (wid > 0 ? wtot[wid - 1] : 0) + part[blockIdx.x];
    if (i < n) {
        off[i]  = excl;
        dinv[i] = rsqrtf((float)c + 1.0f);   // +1 self loop
    }
}

// ---------------------------------------------------------------------------
// CSR build, atomic-free: edge2[off[d] + rank[e]] = {src, norm}.
// ---------------------------------------------------------------------------
__global__ void k_build(const int* __restrict__ src, const int* __restrict__ dst,
                        const int* __restrict__ rank,
                        const int* __restrict__ off,
                        const float* __restrict__ dinv,
                        int2* __restrict__ edge2, int E) {
    int i = blockIdx.x * blockDim.x + threadIdx.x;
    if (i * 2 >= E) return;
    if (i * 2 + 1 < E) {
        int2 s2 = *(const int2*)&src[i * 2];
        int2 d2 = *(const int2*)&dst[i * 2];
        int2 r2 = *(const int2*)&rank[i * 2];
        edge2[off[d2.x] + r2.x] = make_int2(s2.x, __float_as_int(dinv[s2.x] * dinv[d2.x]));
        edge2[off[d2.y] + r2.y] = make_int2(s2.y, __float_as_int(dinv[s2.y] * dinv[d2.y]));
    } else {
        int e = i * 2;
        int s = src[e], d = dst[e];
        edge2[off[d] + rank[e]] = make_int2(s, __float_as_int(dinv[s] * dinv[d]));
    }
}

// ---------------------------------------------------------------------------
// Tiled fp32 GEMM: H[M,N] = op(X)[M,K] @ W[K,N], op = optional relu on X load.
// ---------------------------------------------------------------------------
template <int K, int N, int TM, int KT, bool RELU>
__global__ __launch_bounds__(256) void k_gemm(const float* __restrict__ X,
                                              const float* __restrict__ W,
                                              float* __restrict__ H, int M) {
    constexpr int CT  = N / 4;
    constexpr int RT  = 256 / CT;
    constexpr int RPT = TM / RT;
    constexpr int TMP = TM + 4;       // padded (mult of 4) for aligned LDS.128

    __shared__ float Ws[KT * N];
    __shared__ float Xs[KT * TMP];

    const int t    = threadIdx.x;
    const int row0 = blockIdx.x * TM;
    const int ct   = t % CT;
    const int rt   = t / CT;

    float acc[RPT][4];
#pragma unroll
    for (int r = 0; r < RPT; r++) {
        acc[r][0] = 0.f; acc[r][1] = 0.f; acc[r][2] = 0.f; acc[r][3] = 0.f;
    }

    for (int k0 = 0; k0 < K; k0 += KT) {
        __syncthreads();
        for (int i = t * 4; i < KT * N; i += 1024) {
            *(float4*)&Ws[i] = *(const float4*)&W[k0 * N + i];
        }
        for (int i = t * 4; i < TM * KT; i += 1024) {
            int r  = i / KT;
            int c  = i % KT;
            int gr = row0 + r;
            float4 v = make_float4(0.f, 0.f, 0.f, 0.f);
            if (gr < M) v = *(const float4*)&X[gr * K + k0 + c];
            if (RELU) {
                v.x = fmaxf(v.x, 0.f); v.y = fmaxf(v.y, 0.f);
                v.z = fmaxf(v.z, 0.f); v.w = fmaxf(v.w, 0.f);
            }
            Xs[(c + 0) * TMP + r] = v.x;
            Xs[(c + 1) * TMP + r] = v.y;
            Xs[(c + 2) * TMP + r] = v.z;
            Xs[(c + 3) * TMP + r] = v.w;
        }
        __syncthreads();

#pragma unroll 8
        for (int kk = 0; kk < KT; kk++) {
            float4 w = *(const float4*)&Ws[kk * N + ct * 4];
            float xv[RPT];
#pragma unroll
            for (int rr = 0; rr < RPT; rr += 4) {
                float4 x4 = *(const float4*)&Xs[kk * TMP + rt * RPT + rr];
                xv[rr + 0] = x4.x; xv[rr + 1] = x4.y;
                xv[rr + 2] = x4.z; xv[rr + 3] = x4.w;
            }
#pragma unroll
            for (int r = 0; r < RPT; r++) {
                acc[r][0] = fmaf(xv[r], w.x, acc[r][0]);
                acc[r][1] = fmaf(xv[r], w.y, acc[r][1]);
                acc[r][2] = fmaf(xv[r], w.z, acc[r][2]);
                acc[r][3] = fmaf(xv[r], w.w, acc[r][3]);
            }
        }
    }

#pragma unroll
    for (int r = 0; r < RPT; r++) {
        int gr = row0 + rt * RPT + r;
        if (gr < M) {
            float4 o = make_float4(acc[r][0], acc[r][1], acc[r][2], acc[r][3]);
            *(float4*)&H[gr * N + ct * 4] = o;
        }
    }
}

// ---------------------------------------------------------------------------
// Gather aggregation: WARP per node. Lane = (q channel-group, p edge-partition).
// ---------------------------------------------------------------------------
template <int C>
__global__ __launch_bounds__(256) void k_gather(const float* __restrict__ h,
                                                const int* __restrict__ off,
                                                const int2* __restrict__ edge2,
                                                const float* __restrict__ dinv,
                                                const float* __restrict__ b,
                                                float* __restrict__ out, int M) {
    constexpr int Q = C / 4;
    constexpr int P = 32 / Q;
    const int lane = threadIdx.x & 31;
    const int warp = threadIdx.x >> 5;
    const int i = blockIdx.x * (256 / 32) + warp;
    if (i >= M) return;

    const int q = lane % Q;
    const int p = lane / Q;

    float4 acc = make_float4(0.f, 0.f, 0.f, 0.f);

    const int j1 = off[i + 1];
    int j = off[i] + p;

    for (; j + P < j1; j += 2 * P) {
        int2 eA = __ldg(&edge2[j]);
        int2 eB = __ldg(&edge2[j + P]);
        float wA = __int_as_float(eA.y);
        float wB = __int_as_float(eB.y);
        float4 uA = *(const float4*)&h[eA.x * C + q * 4];
        float4 uB = *(const float4*)&h[eB.x * C + q * 4];
        acc.x = fmaf(wA, uA.x, acc.x); acc.y = fmaf(wA, uA.y, acc.y);
        acc.z = fmaf(wA, uA.z, acc.z); acc.w = fmaf(wA, uA.w, acc.w);
        acc.x = fmaf(wB, uB.x, acc.x); acc.y = fmaf(wB, uB.y, acc.y);
        acc.z = fmaf(wB, uB.z, acc.z); acc.w = fmaf(wB, uB.w, acc.w);
    }
    if (j < j1) {
        int2 e = __ldg(&edge2[j]);
        float w = __int_as_float(e.y);
        float4 u = *(const float4*)&h[e.x * C + q * 4];
        acc.x = fmaf(w, u.x, acc.x); acc.y = fmaf(w, u.y, acc.y);
        acc.z = fmaf(w, u.z, acc.z); acc.w = fmaf(w, u.w, acc.w);
    }

#pragma unroll
    for (int ofs = Q; ofs < 32; ofs <<= 1) {
        acc.x += __shfl_xor_sync(0xffffffffu, acc.x, ofs);
        acc.y += __shfl_xor_sync(0xffffffffu, acc.y, ofs);
        acc.z += __shfl_xor_sync(0xffffffffu, acc.z, ofs);
        acc.w += __shfl_xor_sync(0xffffffffu, acc.w, ofs);
    }

    if (p == 0) {
        const float di = dinv[i];
        const float s2 = di * di;
        float4 bb = *(const float4*)&b[q * 4];
        float4 v  = *(const float4*)&h[i * C + q * 4];
        acc.x += fmaf(s2, v.x, bb.x);
        acc.y += fmaf(s2, v.y, bb.y);
        acc.z += fmaf(s2, v.z, bb.z);
        acc.w += fmaf(s2, v.w, bb.w);
        *(float4*)&out[i * C + q * 4] = acc;
    }
}

// ---------------------------------------------------------------------------
extern "C" void kernel_launch(void* const* d_in, const int* in_sizes, int n_in,
                              void* d_out, int out_size) {
    const float* x   = (const float*)d_in[0];
    const int*   ei  = (const int*)d_in[1];     // int32 (jax x64 disabled)
    const float* W1  = (const float*)d_in[2];
    const float* b1  = (const float*)d_in[3];
    const float* W2  = (const float*)d_in[4];
    const float* b2  = (const float*)d_in[5];
    float*       out = (float*)d_out;

    const int M = in_sizes[0] / INC;       // 100000
    const int E = in_sizes[1] / 2;         // 1600000
    const int* src = ei;
    const int* dst = ei + E;

    float *dinv, *h1, *o1, *h2;
    int *cnt, *off, *rank, *part;
    int2 *edge2;
    cudaGetSymbolAddress((void**)&dinv,  g_dinv);
    cudaGetSymbolAddress((void**)&cnt,   g_cnt);
    cudaGetSymbolAddress((void**)&off,   g_off);
    cudaGetSymbolAddress((void**)&rank,  g_rank);
    cudaGetSymbolAddress((void**)&part,  g_part);
    cudaGetSymbolAddress((void**)&edge2, g_edge2);
    cudaGetSymbolAddress((void**)&h1,    g_h1);
    cudaGetSymbolAddress((void**)&o1,    g_o1);
    cudaGetSymbolAddress((void**)&h2,    g_h2);

    static cudaStream_t sA = nullptr;
    static cudaEvent_t  evF = nullptr, evJ = nullptr;
    if (sA == nullptr) {
        cudaStreamCreateWithFlags(&sA, cudaStreamNonBlocking);
        cudaEventCreateWithFlags(&evF, cudaEventDisableTiming);
        cudaEventCreateWithFlags(&evJ, cudaEventDisableTiming);
    }

    const int B = 256;
    const int WPB = 256 / 32;              // warps (nodes) per gather block
    const int NB = (M + SCB - 1) / SCB;    // scan blocks

    // Fork: CSR build chain on sA, gemm1 on main stream (independent).
    cudaEventRecord(evF, 0);
    cudaStreamWaitEvent(sA, evF, 0);

    cudaMemsetAsync(cnt, 0, M * sizeof(int), sA);
    k_cnt_edge<<<(E / 4 + B - 1) / B, B, 0, sA>>>(dst, cnt, rank, E);
    k_part<<<NB, SCB, 0, sA>>>(cnt, part, M);
    k_scan_part<<<1, 512, 0, sA>>>(part, off, NB, M);
    k_apply<<<NB, SCB, 0, sA>>>(cnt, part, off, dinv, M);
    k_build<<<(E / 2 + B - 1) / B, B, 0, sA>>>(src, dst, rank, off, dinv, edge2, E);
    cudaEventRecord(evJ, sA);

    // layer 1 GEMM runs concurrently with the CSR build
    k_gemm<INC, HID, 128, 32, false><<<(M + 127) / 128, 256>>>(x, W1, h1, M);

    // Join, then the serial tail
    cudaStreamWaitEvent(0, evJ, 0);
    k_gather<HID><<<(M + WPB - 1) / WPB, B>>>(h1, off, edge2, dinv, b1, o1, M);
    k_gemm<HID, OUTC, 128, 32, true><<<(M + 127) / 128, 256>>>(o1, W2, h2, M);
    k_gather<OUTC><<<(M + WPB - 1) / WPB, B>>>(h2, off, edge2, dinv, b2, out, M);
}